// round 1
// baseline (speedup 1.0000x reference)
#include <cuda_runtime.h>
#include <cstdint>

// Problem constants (fixed shapes per reference)
#define M_TOK   65536          // N*L = 16*4096
#define FEATD   512
#define H1D     1024
#define NAA     21
#define CRD     42             // 14*3
#define EPSF    1e-6f

// -------- static device scratch (no runtime allocation allowed) ----------
__device__ float g_crd[(size_t)M_TOK * CRD];      // 11 MB  local coords
__device__ float g_table[NAA * H1D];              // 84 KB  embed[aa]@w1[882:]+b1
__device__ float g_h1[(size_t)M_TOK * H1D];       // 256 MB
__device__ float g_h2[(size_t)M_TOK * FEATD];     // 128 MB
__device__ int   g_mask_mode;                     // 0=int32, 1=float32, 2=byte

// ---------------------------------------------------------------------------
// Detect the on-device dtype of atom_mask (JAX bool -> unknown canonical type).
// Deterministic pure function of the input; graph-capturable.
// ---------------------------------------------------------------------------
__global__ void detect_mask_kernel(const unsigned int* __restrict__ m, int n_words)
{
    __shared__ int sawFloat, sawBig;
    int tid = threadIdx.x;
    if (tid == 0) { sawFloat = 0; sawBig = 0; }
    __syncthreads();
    for (int i = tid; i < n_words; i += blockDim.x) {
        unsigned v = m[i];
        if (v == 0x3F800000u)      sawFloat = 1;   // 1.0f pattern
        else if (v > 1u)           sawBig   = 1;   // packed bytes like 0x01010101
    }
    __syncthreads();
    if (tid == 0) g_mask_mode = sawFloat ? 1 : (sawBig ? 2 : 0);
}

__device__ __forceinline__ bool read_mask(const void* m, int mode, size_t i)
{
    if (mode == 0) return ((const int*)m)[i] != 0;
    if (mode == 1) return ((const float*)m)[i] != 0.0f;
    return ((const unsigned char*)m)[i] != 0;
}

// ---------------------------------------------------------------------------
// Frame construction: per token build (e1,e2,e3) and rotate+mask 14 atoms.
// 128 tokens per block, staged through shared memory for coalescing.
// ---------------------------------------------------------------------------
__global__ void __launch_bounds__(128) frame_kernel(
    const float* __restrict__ pos14, const void* __restrict__ maskp)
{
    __shared__ float sp[128 * CRD];
    const int tid  = threadIdx.x;
    const int base = blockIdx.x * 128;

    // coalesced stage-in of pos14 for 128 tokens
    const size_t gbase = (size_t)base * CRD;
    #pragma unroll 4
    for (int i = tid; i < 128 * CRD; i += 128) sp[i] = pos14[gbase + i];
    __syncthreads();

    const float* p = &sp[tid * CRD];
    const int t = base + tid;

    const float cx = p[3], cy = p[4], cz = p[5];           // atom 1 = center
    float v1x = p[6] - cx, v1y = p[7] - cy, v1z = p[8] - cz;   // atom 2
    float n1 = sqrtf(v1x*v1x + v1y*v1y + v1z*v1z) + EPSF;
    float e1x = v1x / n1, e1y = v1y / n1, e1z = v1z / n1;

    float v2x = p[0] - cx, v2y = p[1] - cy, v2z = p[2] - cz;   // atom 0
    float d = e1x*v2x + e1y*v2y + e1z*v2z;
    float u2x = v2x - d*e1x, u2y = v2y - d*e1y, u2z = v2z - d*e1z;
    float n2 = sqrtf(u2x*u2x + u2y*u2y + u2z*u2z) + EPSF;
    float e2x = u2x / n2, e2y = u2y / n2, e2z = u2z / n2;

    float e3x = e1y*e2z - e1z*e2y;
    float e3y = e1z*e2x - e1x*e2z;
    float e3z = e1x*e2y - e1y*e2x;

    const int mode = g_mask_mode;
    float r[CRD];
    #pragma unroll
    for (int a = 0; a < 14; a++) {
        float qx = p[a*3+0] - cx, qy = p[a*3+1] - cy, qz = p[a*3+2] - cz;
        bool mk = read_mask(maskp, mode, (size_t)t * 14 + a);
        r[a*3+0] = mk ? (e1x*qx + e1y*qy + e1z*qz) : 0.0f;
        r[a*3+1] = mk ? (e2x*qx + e2y*qy + e2z*qz) : 0.0f;
        r[a*3+2] = mk ? (e3x*qx + e3y*qy + e3z*qz) : 0.0f;
    }
    __syncthreads();
    #pragma unroll
    for (int i = 0; i < CRD; i++) sp[tid * CRD + i] = r[i];
    __syncthreads();
    #pragma unroll 4
    for (int i = tid; i < 128 * CRD; i += 128) g_crd[gbase + i] = sp[i];
}

// ---------------------------------------------------------------------------
// Precompute table[aa][j] = embed[aa] @ w1[882:1394, j] + b1[j]
// 21 blocks x 256 threads, 4 outputs per thread (float4).
// ---------------------------------------------------------------------------
__global__ void __launch_bounds__(256) embproj_kernel(
    const float* __restrict__ embed, const float* __restrict__ w1,
    const float* __restrict__ b1)
{
    __shared__ float se[FEATD];
    const int a = blockIdx.x;
    const int tid = threadIdx.x;
    for (int i = tid; i < FEATD; i += 256) se[i] = embed[a * FEATD + i];
    __syncthreads();

    const int j = tid * 4;
    float4 acc = *(const float4*)(b1 + j);
    const float* wp = w1 + (size_t)(NAA * CRD) * H1D + j;   // rows 882..1393
    #pragma unroll 4
    for (int f = 0; f < FEATD; f++) {
        float e = se[f];
        float4 w = *(const float4*)(wp + (size_t)f * H1D);
        acc.x += e * w.x; acc.y += e * w.y; acc.z += e * w.z; acc.w += e * w.w;
    }
    *(float4*)(&g_table[a * H1D + j]) = acc;
}

// ---------------------------------------------------------------------------
// Layer 1 (sparse): h1[m][j] = relu( crd42[m] . w1[aa*42 .. +41][j] + table[aa][j] )
// One block per token, 256 threads, 4 outputs per thread (float4 w1 loads).
// ---------------------------------------------------------------------------
__global__ void __launch_bounds__(256) layer1_kernel(
    const int* __restrict__ aa, const float* __restrict__ w1)
{
    __shared__ float sc[CRD];
    __shared__ int sa;
    const int m = blockIdx.x;
    const int tid = threadIdx.x;
    if (tid == 0) sa = aa[m];
    if (tid < CRD) sc[tid] = g_crd[(size_t)m * CRD + tid];
    __syncthreads();

    const int a = sa;
    const int j = tid * 4;
    float4 acc = *(const float4*)(&g_table[a * H1D + j]);
    const float* wp = w1 + (size_t)(a * CRD) * H1D + j;
    #pragma unroll
    for (int k = 0; k < CRD; k++) {
        float c = sc[k];
        float4 w = *(const float4*)(wp + (size_t)k * H1D);
        acc.x += c * w.x; acc.y += c * w.y; acc.z += c * w.z; acc.w += c * w.w;
    }
    acc.x = fmaxf(acc.x, 0.f); acc.y = fmaxf(acc.y, 0.f);
    acc.z = fmaxf(acc.z, 0.f); acc.w = fmaxf(acc.w, 0.f);
    *(float4*)(&g_h1[(size_t)m * H1D + j]) = acc;
}

// ---------------------------------------------------------------------------
// Dense GEMM with fused bias + optional ReLU: C[M,N] = act(A[M,K] @ W[K,N] + b)
// Tile 128x64x16, 256 threads, 8x4 per thread, fp32 SIMT.
// Requires M%128==0, N%64==0, K%16==0 (holds for all layers here).
// ---------------------------------------------------------------------------
__global__ void __launch_bounds__(256) gemm_bias_act(
    const float* __restrict__ A, const float* __restrict__ W,
    const float* __restrict__ bias, float* __restrict__ C,
    int M, int K, int N, int relu)
{
    __shared__ float As[16][128];   // k-major (transposed) for conflict-free reads
    __shared__ float Ws[16][64];

    const int tid = threadIdx.x;
    const int tx = tid & 15;            // column group  (0..15) -> 4 cols each
    const int ty = tid >> 4;            // row group     (0..15) -> 8 rows each
    const int row0 = blockIdx.y * 128;
    const int col0 = blockIdx.x * 64;

    float acc[8][4];
    #pragma unroll
    for (int i = 0; i < 8; i++)
        #pragma unroll
        for (int j = 0; j < 4; j++) acc[i][j] = 0.0f;

    for (int k0 = 0; k0 < K; k0 += 16) {
        // stage A tile (128x16) transposed into As[k][row]: 512 float4, 2/thread
        #pragma unroll
        for (int l = 0; l < 2; l++) {
            int idx = tid + l * 256;        // 0..511
            int r   = idx >> 2;             // 0..127
            int kq  = idx & 3;              // 0..3
            float4 v = *(const float4*)(A + (size_t)(row0 + r) * K + k0 + kq * 4);
            As[kq*4+0][r] = v.x; As[kq*4+1][r] = v.y;
            As[kq*4+2][r] = v.z; As[kq*4+3][r] = v.w;
        }
        // stage W tile (16x64): 256 float4, 1/thread
        {
            int wr = tid >> 4;              // k within tile
            int wc = tid & 15;              // col/4
            float4 v = *(const float4*)(W + (size_t)(k0 + wr) * N + col0 + wc * 4);
            *(float4*)&Ws[wr][wc * 4] = v;
        }
        __syncthreads();

        #pragma unroll
        for (int kk = 0; kk < 16; kk++) {
            float4 a0 = *(const float4*)&As[kk][ty * 8];
            float4 a1 = *(const float4*)&As[kk][ty * 8 + 4];
            float4 b  = *(const float4*)&Ws[kk][tx * 4];
            float av[8] = {a0.x, a0.y, a0.z, a0.w, a1.x, a1.y, a1.z, a1.w};
            float bv[4] = {b.x, b.y, b.z, b.w};
            #pragma unroll
            for (int i = 0; i < 8; i++)
                #pragma unroll
                for (int j = 0; j < 4; j++)
                    acc[i][j] += av[i] * bv[j];
        }
        __syncthreads();
    }

    float4 bb = *(const float4*)(bias + col0 + tx * 4);
    #pragma unroll
    for (int i = 0; i < 8; i++) {
        float4 o;
        o.x = acc[i][0] + bb.x; o.y = acc[i][1] + bb.y;
        o.z = acc[i][2] + bb.z; o.w = acc[i][3] + bb.w;
        if (relu) {
            o.x = fmaxf(o.x, 0.f); o.y = fmaxf(o.y, 0.f);
            o.z = fmaxf(o.z, 0.f); o.w = fmaxf(o.w, 0.f);
        }
        *(float4*)(C + (size_t)(row0 + ty * 8 + i) * N + col0 + tx * 4) = o;
    }
}

// Helper kernels reference globals directly; fetch raw pointers via symbols.
extern "C" void kernel_launch(void* const* d_in, const int* in_sizes, int n_in,
                              void* d_out, int out_size)
{
    // Input order per reference setup_inputs():
    // 0 aa(int32 N*L)        1 pos14(f32 N*L*14*3)   2 atom_mask(bool N*L*14)
    // 3 embed(f32 21*512)    4 w1(f32 1394*1024)     5 b1(1024)
    // 6 w2(1024*512)         7 b2(512)               8 w3(512*512)
    // 9 b3(512)             10 w4(512*512)          11 b4(512)
    const int*   aa    = (const int*)  d_in[0];
    const float* pos14 = (const float*)d_in[1];
    const void*  amask =               d_in[2];
    const float* embed = (const float*)d_in[3];
    const float* w1    = (const float*)d_in[4];
    const float* b1    = (const float*)d_in[5];
    const float* w2    = (const float*)d_in[6];
    const float* b2    = (const float*)d_in[7];
    const float* w3    = (const float*)d_in[8];
    const float* b3    = (const float*)d_in[9];
    const float* w4    = (const float*)d_in[10];
    const float* b4    = (const float*)d_in[11];
    float* out = (float*)d_out;

    float *p_h1, *p_h2;
    cudaGetSymbolAddress((void**)&p_h1, g_h1);
    cudaGetSymbolAddress((void**)&p_h2, g_h2);

    // 1) sniff atom_mask dtype (first 4096 words; safe for all encodings)
    detect_mask_kernel<<<1, 256>>>((const unsigned int*)amask, 4096);

    // 2) local-frame construction + masked rotation -> g_crd
    frame_kernel<<<M_TOK / 128, 128>>>(pos14, amask);

    // 3) tiny precompute: table[aa] = embed[aa] @ w1[882:] + b1
    embproj_kernel<<<NAA, 256>>>(embed, w1, b1);

    // 4) sparse layer 1 -> g_h1 (relu)
    layer1_kernel<<<M_TOK, 256>>>(aa, w1);

    // 5..7) dense MLP
    {
        dim3 blk(256);
        dim3 g2(FEATD / 64, M_TOK / 128);
        gemm_bias_act<<<g2, blk>>>(p_h1, w2, b2, p_h2, M_TOK, H1D,  FEATD, 1);
        gemm_bias_act<<<g2, blk>>>(p_h2, w3, b3, p_h1, M_TOK, FEATD, FEATD, 1);
        gemm_bias_act<<<g2, blk>>>(p_h1, w4, b4, out,  M_TOK, FEATD, FEATD, 0);
    }
}

// round 2
// speedup vs baseline: 3.9390x; 3.9390x over previous
#include <cuda_runtime.h>
#include <cstdint>

// Problem constants (fixed shapes per reference)
#define M_TOK   65536          // N*L = 16*4096
#define FEATD   512
#define H1D     1024
#define NAA     21
#define CRD     42             // 14*3
#define EPSF    1e-6f

// -------- static device scratch (no runtime allocation allowed) ----------
__device__ float g_crd[(size_t)M_TOK * CRD];      // 11 MB  local coords
__device__ float g_table[NAA * H1D];              // 84 KB  embed[aa]@w1[882:]+b1
__device__ float g_h1[(size_t)M_TOK * H1D];       // 256 MB
__device__ float g_h2[(size_t)M_TOK * FEATD];     // 128 MB
__device__ int   g_mask_mode;                     // 0=int32, 1=float32, 2=byte

// ---------------------------------------------------------------------------
// Detect the on-device dtype of atom_mask (JAX bool -> unknown canonical type).
// ---------------------------------------------------------------------------
__global__ void detect_mask_kernel(const unsigned int* __restrict__ m, int n_words)
{
    __shared__ int sawFloat, sawBig;
    int tid = threadIdx.x;
    if (tid == 0) { sawFloat = 0; sawBig = 0; }
    __syncthreads();
    for (int i = tid; i < n_words; i += blockDim.x) {
        unsigned v = m[i];
        if (v == 0x3F800000u)      sawFloat = 1;   // 1.0f pattern
        else if (v > 1u)           sawBig   = 1;   // packed bytes like 0x01010101
    }
    __syncthreads();
    if (tid == 0) g_mask_mode = sawFloat ? 1 : (sawBig ? 2 : 0);
}

__device__ __forceinline__ bool read_mask(const void* m, int mode, size_t i)
{
    if (mode == 0) return ((const int*)m)[i] != 0;
    if (mode == 1) return ((const float*)m)[i] != 0.0f;
    return ((const unsigned char*)m)[i] != 0;
}

// ---------------------------------------------------------------------------
// Frame construction: per token build (e1,e2,e3) and rotate+mask 14 atoms.
// ---------------------------------------------------------------------------
__global__ void __launch_bounds__(128) frame_kernel(
    const float* __restrict__ pos14, const void* __restrict__ maskp)
{
    __shared__ float sp[128 * CRD];
    const int tid  = threadIdx.x;
    const int base = blockIdx.x * 128;

    const size_t gbase = (size_t)base * CRD;
    #pragma unroll 4
    for (int i = tid; i < 128 * CRD; i += 128) sp[i] = pos14[gbase + i];
    __syncthreads();

    const float* p = &sp[tid * CRD];
    const int t = base + tid;

    const float cx = p[3], cy = p[4], cz = p[5];
    float v1x = p[6] - cx, v1y = p[7] - cy, v1z = p[8] - cz;
    float n1 = sqrtf(v1x*v1x + v1y*v1y + v1z*v1z) + EPSF;
    float e1x = v1x / n1, e1y = v1y / n1, e1z = v1z / n1;

    float v2x = p[0] - cx, v2y = p[1] - cy, v2z = p[2] - cz;
    float d = e1x*v2x + e1y*v2y + e1z*v2z;
    float u2x = v2x - d*e1x, u2y = v2y - d*e1y, u2z = v2z - d*e1z;
    float n2 = sqrtf(u2x*u2x + u2y*u2y + u2z*u2z) + EPSF;
    float e2x = u2x / n2, e2y = u2y / n2, e2z = u2z / n2;

    float e3x = e1y*e2z - e1z*e2y;
    float e3y = e1z*e2x - e1x*e2z;
    float e3z = e1x*e2y - e1y*e2x;

    const int mode = g_mask_mode;
    float r[CRD];
    #pragma unroll
    for (int a = 0; a < 14; a++) {
        float qx = p[a*3+0] - cx, qy = p[a*3+1] - cy, qz = p[a*3+2] - cz;
        bool mk = read_mask(maskp, mode, (size_t)t * 14 + a);
        r[a*3+0] = mk ? (e1x*qx + e1y*qy + e1z*qz) : 0.0f;
        r[a*3+1] = mk ? (e2x*qx + e2y*qy + e2z*qz) : 0.0f;
        r[a*3+2] = mk ? (e3x*qx + e3y*qy + e3z*qz) : 0.0f;
    }
    __syncthreads();
    #pragma unroll
    for (int i = 0; i < CRD; i++) sp[tid * CRD + i] = r[i];
    __syncthreads();
    #pragma unroll 4
    for (int i = tid; i < 128 * CRD; i += 128) g_crd[gbase + i] = sp[i];
}

// ---------------------------------------------------------------------------
// Precompute table[aa][j] = embed[aa] @ w1[882:1394, j] + b1[j]
// ---------------------------------------------------------------------------
__global__ void __launch_bounds__(256) embproj_kernel(
    const float* __restrict__ embed, const float* __restrict__ w1,
    const float* __restrict__ b1)
{
    __shared__ float se[FEATD];
    const int a = blockIdx.x;
    const int tid = threadIdx.x;
    for (int i = tid; i < FEATD; i += 256) se[i] = embed[a * FEATD + i];
    __syncthreads();

    const int j = tid * 4;
    float4 acc = *(const float4*)(b1 + j);
    const float* wp = w1 + (size_t)(NAA * CRD) * H1D + j;
    #pragma unroll 4
    for (int f = 0; f < FEATD; f++) {
        float e = se[f];
        float4 w = *(const float4*)(wp + (size_t)f * H1D);
        acc.x += e * w.x; acc.y += e * w.y; acc.z += e * w.z; acc.w += e * w.w;
    }
    *(float4*)(&g_table[a * H1D + j]) = acc;
}

// ---------------------------------------------------------------------------
// Layer 1 (sparse): h1[m][j] = relu( crd42[m] . w1[aa*42 .. +41][j] + table[aa][j] )
// ---------------------------------------------------------------------------
__global__ void __launch_bounds__(256) layer1_kernel(
    const int* __restrict__ aa, const float* __restrict__ w1)
{
    __shared__ float sc[CRD];
    __shared__ int sa;
    const int m = blockIdx.x;
    const int tid = threadIdx.x;
    if (tid == 0) sa = aa[m];
    if (tid < CRD) sc[tid] = g_crd[(size_t)m * CRD + tid];
    __syncthreads();

    const int a = sa;
    const int j = tid * 4;
    float4 acc = *(const float4*)(&g_table[a * H1D + j]);
    const float* wp = w1 + (size_t)(a * CRD) * H1D + j;
    #pragma unroll
    for (int k = 0; k < CRD; k++) {
        float c = sc[k];
        float4 w = *(const float4*)(wp + (size_t)k * H1D);
        acc.x += c * w.x; acc.y += c * w.y; acc.z += c * w.z; acc.w += c * w.w;
    }
    acc.x = fmaxf(acc.x, 0.f); acc.y = fmaxf(acc.y, 0.f);
    acc.z = fmaxf(acc.z, 0.f); acc.w = fmaxf(acc.w, 0.f);
    *(float4*)(&g_h1[(size_t)m * H1D + j]) = acc;
}

// ---------------------------------------------------------------------------
// tf32 tensor-core GEMM with fused bias + optional ReLU.
// C[M,N] = act(A[M,K] @ W[K,N] + b).  Tile 128x128x32, 256 thr (8 warps),
// warp tile 64x32, mma.sync.m16n8k8.tf32.  M%128==0, N%128==0, K%32==0.
// ---------------------------------------------------------------------------
__device__ __forceinline__ unsigned f2tf32(float x)
{
    float r;
    asm("cvt.rna.tf32.f32 %0, %1;" : "=f"(r) : "f"(x));
    return __float_as_uint(r);
}

__global__ void __launch_bounds__(256) gemm_tf32(
    const float* __restrict__ A, const float* __restrict__ W,
    const float* __restrict__ bias, float* __restrict__ C,
    int M, int K, int N, int relu)
{
    __shared__ unsigned As[128][36];    // [m][k], pad 4 -> conflict-free frag loads
    __shared__ unsigned Ws[32][136];    // [k][n], pad 8 -> conflict-free frag loads

    const int tid  = threadIdx.x;
    const int wid  = tid >> 5;
    const int lane = tid & 31;
    const int gid  = lane >> 2;         // 0..7
    const int tig  = lane & 3;          // 0..3
    const int warpM = (wid >> 2) * 64;  // 0 or 64
    const int warpN = (wid & 3) * 32;   // 0,32,64,96
    const int row0 = blockIdx.y * 128;
    const int col0 = blockIdx.x * 128;

    float acc[4][4][4];                 // [mfrag][nfrag][c0..c3]
    #pragma unroll
    for (int i = 0; i < 4; i++)
        #pragma unroll
        for (int j = 0; j < 4; j++)
            #pragma unroll
            for (int c = 0; c < 4; c++) acc[i][j][c] = 0.0f;

    for (int k0 = 0; k0 < K; k0 += 32) {
        // stage A tile 128x32 (1024 float4 slots, 4 per thread)
        #pragma unroll
        for (int l = 0; l < 4; l++) {
            int s  = tid + l * 256;
            int r  = s >> 3;
            int kq = s & 7;
            float4 v = *(const float4*)(A + (size_t)(row0 + r) * K + k0 + kq * 4);
            As[r][kq*4+0] = f2tf32(v.x); As[r][kq*4+1] = f2tf32(v.y);
            As[r][kq*4+2] = f2tf32(v.z); As[r][kq*4+3] = f2tf32(v.w);
        }
        // stage W tile 32x128 (1024 float4 slots, 4 per thread)
        #pragma unroll
        for (int l = 0; l < 4; l++) {
            int s  = tid + l * 256;
            int kr = s >> 5;
            int nc = s & 31;
            float4 v = *(const float4*)(W + (size_t)(k0 + kr) * N + col0 + nc * 4);
            Ws[kr][nc*4+0] = f2tf32(v.x); Ws[kr][nc*4+1] = f2tf32(v.y);
            Ws[kr][nc*4+2] = f2tf32(v.z); Ws[kr][nc*4+3] = f2tf32(v.w);
        }
        __syncthreads();

        #pragma unroll
        for (int kt = 0; kt < 32; kt += 8) {
            unsigned af[4][4], bf[4][2];
            #pragma unroll
            for (int mf = 0; mf < 4; mf++) {
                int r = warpM + mf * 16 + gid;
                af[mf][0] = As[r    ][kt + tig];
                af[mf][1] = As[r + 8][kt + tig];
                af[mf][2] = As[r    ][kt + tig + 4];
                af[mf][3] = As[r + 8][kt + tig + 4];
            }
            #pragma unroll
            for (int nf = 0; nf < 4; nf++) {
                int c = warpN + nf * 8 + gid;
                bf[nf][0] = Ws[kt + tig    ][c];
                bf[nf][1] = Ws[kt + tig + 4][c];
            }
            #pragma unroll
            for (int mf = 0; mf < 4; mf++)
                #pragma unroll
                for (int nf = 0; nf < 4; nf++)
                    asm volatile(
                        "mma.sync.aligned.m16n8k8.row.col.f32.tf32.tf32.f32 "
                        "{%0,%1,%2,%3}, {%4,%5,%6,%7}, {%8,%9}, {%0,%1,%2,%3};"
                        : "+f"(acc[mf][nf][0]), "+f"(acc[mf][nf][1]),
                          "+f"(acc[mf][nf][2]), "+f"(acc[mf][nf][3])
                        : "r"(af[mf][0]), "r"(af[mf][1]), "r"(af[mf][2]), "r"(af[mf][3]),
                          "r"(bf[nf][0]), "r"(bf[nf][1]));
        }
        __syncthreads();
    }

    // epilogue: bias + optional relu, float2 stores (c pairs are adjacent cols)
    #pragma unroll
    for (int nf = 0; nf < 4; nf++) {
        int c = col0 + warpN + nf * 8 + 2 * tig;
        float bx = bias[c], by = bias[c + 1];
        #pragma unroll
        for (int mf = 0; mf < 4; mf++) {
            int r = row0 + warpM + mf * 16 + gid;
            float2 o0, o1;
            o0.x = acc[mf][nf][0] + bx; o0.y = acc[mf][nf][1] + by;
            o1.x = acc[mf][nf][2] + bx; o1.y = acc[mf][nf][3] + by;
            if (relu) {
                o0.x = fmaxf(o0.x, 0.f); o0.y = fmaxf(o0.y, 0.f);
                o1.x = fmaxf(o1.x, 0.f); o1.y = fmaxf(o1.y, 0.f);
            }
            *(float2*)(C + (size_t)r * N + c)       = o0;
            *(float2*)(C + (size_t)(r + 8) * N + c) = o1;
        }
    }
}

extern "C" void kernel_launch(void* const* d_in, const int* in_sizes, int n_in,
                              void* d_out, int out_size)
{
    const int*   aa    = (const int*)  d_in[0];
    const float* pos14 = (const float*)d_in[1];
    const void*  amask =               d_in[2];
    const float* embed = (const float*)d_in[3];
    const float* w1    = (const float*)d_in[4];
    const float* b1    = (const float*)d_in[5];
    const float* w2    = (const float*)d_in[6];
    const float* b2    = (const float*)d_in[7];
    const float* w3    = (const float*)d_in[8];
    const float* b3    = (const float*)d_in[9];
    const float* w4    = (const float*)d_in[10];
    const float* b4    = (const float*)d_in[11];
    float* out = (float*)d_out;

    float *p_h1, *p_h2;
    cudaGetSymbolAddress((void**)&p_h1, g_h1);
    cudaGetSymbolAddress((void**)&p_h2, g_h2);

    detect_mask_kernel<<<1, 256>>>((const unsigned int*)amask, 4096);
    frame_kernel<<<M_TOK / 128, 128>>>(pos14, amask);
    embproj_kernel<<<NAA, 256>>>(embed, w1, b1);
    layer1_kernel<<<M_TOK, 256>>>(aa, w1);

    {
        dim3 blk(256);
        dim3 g2(FEATD / 128, M_TOK / 128);   // (4, 512)
        gemm_tf32<<<g2, blk>>>(p_h1, w2, b2, p_h2, M_TOK, H1D,  FEATD, 1);
        gemm_tf32<<<g2, blk>>>(p_h2, w3, b3, p_h1, M_TOK, FEATD, FEATD, 1);
        gemm_tf32<<<g2, blk>>>(p_h1, w4, b4, out,  M_TOK, FEATD, FEATD, 0);
    }
}